// round 10
// baseline (speedup 1.0000x reference)
#include <cuda_runtime.h>
#include <math.h>

#define NCH    256
#define PLANE  4096        // 64*64
#define PITCH  68          // smem row pitch (floats): 16B-aligned, 4-row stride = 272 % 32 = 16 banks (conflict-free)
#define SROWS  68          // 64 rows + 2-row halo top/bottom
#define ROFF   2
#define GRID   592         // 148 SMs * 4 resident CTAs
#define NPLANES 4096       // 16 batches * 256 channels

__device__ __forceinline__ float4 fmax4(float4 a, float4 b) {
    return make_float4(fmaxf(a.x, b.x), fmaxf(a.y, b.y),
                       fmaxf(a.z, b.z), fmaxf(a.w, b.w));
}

__global__ void __launch_bounds__(256, 4)
spp_kernel(const float* __restrict__ x, float* __restrict__ out) {
    __shared__ float s[SROWS][PITCH];

    const int tid = threadIdx.x;

    // ---- init ONLY the row-halo rows (0,1,66,67) to -inf — once per block ----
    for (int i = tid; i < 2 * PITCH; i += 256) {
        int r = i / PITCH, c = i % PITCH;
        s[r][c]      = -INFINITY;
        s[66 + r][c] = -INFINITY;
    }

    // each thread owns a 4x4 tile
    const int tr = (tid >> 4) << 2;     // tile row base: 0..60
    const int tc = (tid & 15) << 2;     // tile col base: 0..60
    const int ct = tid & 15;            // column tile index (0..15)
    const int base = (tr << 4) + (tc >> 2);   // float4 index of tile origin in a plane

    int plane = blockIdx.x;

    // ---- prologue: load first plane ----
    float4 v[4];
    {
        const float4* in4 = (const float4*)(x + (size_t)plane * PLANE) + base;
        #pragma unroll
        for (int rr = 0; rr < 4; rr++) v[rr] = in4[rr << 4];
    }
    __syncthreads();   // halo init visible

    while (true) {
        const int batch = plane >> 8;
        const int ch    = plane & 255;
        float4* o0 = (float4*)(out + ((size_t)batch * 4 * NCH + ch) * PLANE) + base;

        // ---- passthrough copy to group 0 ----
        #pragma unroll
        for (int rr = 0; rr < 4; rr++) o0[rr << 4] = v[rr];

        // ---- prefetch next plane; completes under the 3 pools' compute ----
        const int next = plane + GRID;
        float4 nv[4];
        if (next < NPLANES) {
            const float4* in4 = (const float4*)(x + (size_t)next * PLANE) + base;
            #pragma unroll
            for (int rr = 0; rr < 4; rr++) nv[rr] = in4[rr << 4];
        }

        // ---- three chained window-5 pools: mp5, mp9 = mp5^2, mp13 = mp5^3 ----
        float4* ogp = o0;
        #pragma unroll
        for (int g = 1; g <= 3; g++) {
            // horizontal window-5 max via warp shuffle; overwrite v in place
            #pragma unroll
            for (int rr = 0; rr < 4; rr++) {
                float4 a = v[rr];
                float lz = __shfl_up_sync(0xFFFFFFFFu, a.z, 1);   // col tc-2
                float lw = __shfl_up_sync(0xFFFFFFFFu, a.w, 1);   // col tc-1
                float rx = __shfl_down_sync(0xFFFFFFFFu, a.x, 1); // col tc+4
                float ry = __shfl_down_sync(0xFFFFFFFFu, a.y, 1); // col tc+5
                if (ct == 0)  { lz = -INFINITY; lw = -INFINITY; } // image left border
                if (ct == 15) { rx = -INFINITY; ry = -INFINITY; } // image right border

                float cyz = fmaxf(a.y, a.z);
                float cxw = fmaxf(a.x, a.w);
                float m4  = fmaxf(cyz, cxw);                 // max(x,y,z,w)
                float4 h;
                h.x = fmaxf(fmaxf(lz, lw), fmaxf(a.x, cyz));    // cols tc-2..tc+2
                h.y = fmaxf(lw, m4);                            // cols tc-1..tc+3
                h.z = fmaxf(m4, rx);                            // cols tc  ..tc+4
                h.w = fmaxf(cyz, fmaxf(a.w, fmaxf(rx, ry)));    // cols tc+1..tc+5
                v[rr] = h;                                      // H result replaces input
                *(float4*)&s[tr + rr + ROFF][tc] = h;           // row exchange for V halo
            }
            __syncthreads();

            // halo rows: tr-2, tr-1, tr+4, tr+5 (padded indices tr+0, tr+1, tr+6, tr+7)
            float4 um2 = *(const float4*)&s[tr + 0][tc];
            float4 um1 = *(const float4*)&s[tr + 1][tc];
            float4 up4 = *(const float4*)&s[tr + 6][tc];
            float4 up5 = *(const float4*)&s[tr + 7][tc];

            // vertical window-5 max in registers
            float4 m12 = fmax4(v[1], v[2]);
            float4 m03 = fmax4(v[0], v[3]);
            float4 m4  = fmax4(m12, m03);
            float4 y0 = fmax4(fmax4(um2, um1), fmax4(v[0], m12));
            float4 y1 = fmax4(um1, m4);
            float4 y2 = fmax4(m4, up4);
            float4 y3 = fmax4(m12, fmax4(v[3], fmax4(up4, up5)));

            // store to output group g; keep as input for next pool
            ogp += NCH * PLANE / 4;
            ogp[ 0] = y0;
            ogp[16] = y1;
            ogp[32] = y2;
            ogp[48] = y3;

            v[0] = y0; v[1] = y1; v[2] = y2; v[3] = y3;
            __syncthreads();   // WAR: s is rewritten next pool / next iteration
        }

        if (next >= NPLANES) break;
        plane = next;
        #pragma unroll
        for (int rr = 0; rr < 4; rr++) v[rr] = nv[rr];
    }
}

extern "C" void kernel_launch(void* const* d_in, const int* in_sizes, int n_in,
                              void* d_out, int out_size) {
    const float* x = (const float*)d_in[0];
    float* out = (float*)d_out;
    spp_kernel<<<GRID, 256>>>(x, out);
}

// round 11
// speedup vs baseline: 1.1590x; 1.1590x over previous
#include <cuda_runtime.h>
#include <math.h>

#define NCH   256
#define PLANE 4096         // 64*64
#define PITCH 68           // smem row pitch (floats): 16B-aligned, 4-row stride = 272 % 32 = 16 banks (conflict-free)
#define SROWS 68           // 64 rows + 2-row halo top/bottom
#define ROFF  2

__device__ __forceinline__ float4 fmax4(float4 a, float4 b) {
    return make_float4(fmaxf(a.x, b.x), fmaxf(a.y, b.y),
                       fmaxf(a.z, b.z), fmaxf(a.w, b.w));
}

__global__ void __launch_bounds__(256)
spp_kernel(const float* __restrict__ x, float* __restrict__ out) {
    __shared__ float s[2][SROWS][PITCH];   // one buffer per plane

    const int tid    = threadIdx.x;
    const int plane0 = blockIdx.x << 1;    // two adjacent channels per block
    const int batch  = plane0 >> 8;
    const int ch0    = plane0 & 255;       // even; ch1 = ch0+1 (same batch, adjacent)

    const float4* in4a = (const float4*)(x + (size_t)plane0 * PLANE);
    const float4* in4b = in4a + PLANE / 4;

    float* o0 = out + ((size_t)batch * 4 * NCH + ch0) * PLANE;  // group-0 base, plane 0

    // ---- init ONLY the row-halo rows (0,1,66,67) of both buffers to -inf ----
    for (int i = tid; i < 2 * PITCH; i += 256) {
        int r = i / PITCH, c = i % PITCH;
        s[0][r][c]      = -INFINITY;
        s[0][66 + r][c] = -INFINITY;
        s[1][r][c]      = -INFINITY;
        s[1][66 + r][c] = -INFINITY;
    }

    // each thread owns a 4x4 tile in each plane
    const int tr = (tid >> 4) << 2;     // tile row base: 0..60
    const int tc = (tid & 15) << 2;     // tile col base: 0..60
    const int ct = tid & 15;            // column tile index (0..15)

    const int base = (tr << 4) + (tc >> 2);   // float4 index of tile origin in a plane

    // ---- load both planes (8 independent LDG.128) + passthrough copy to group 0 ----
    float4 v[2][4];
    #pragma unroll
    for (int rr = 0; rr < 4; rr++) {
        v[0][rr] = in4a[base + (rr << 4)];
        v[1][rr] = in4b[base + (rr << 4)];
    }
    {
        float4* o4a = (float4*)o0;
        float4* o4b = o4a + PLANE / 4;
        #pragma unroll
        for (int rr = 0; rr < 4; rr++) {
            __stcs(&o4a[base + (rr << 4)], v[0][rr]);   // streaming: write-once, never read
            __stcs(&o4b[base + (rr << 4)], v[1][rr]);
        }
    }

    float4* ogp = (float4*)o0 + base;   // walked by +NCH*PLANE/4 per group; +PLANE/4 selects plane 1

    __syncthreads();   // covers halo init

    // three chained window-5 pools: mp5, mp9 = mp5^2, mp13 = mp5^3
    #pragma unroll
    for (int g = 1; g <= 3; g++) {
        // ---- horizontal window-5 max via warp shuffle; overwrite v in place ----
        #pragma unroll
        for (int p = 0; p < 2; p++) {
            #pragma unroll
            for (int rr = 0; rr < 4; rr++) {
                float4 a = v[p][rr];
                float lz = __shfl_up_sync(0xFFFFFFFFu, a.z, 1);   // col tc-2
                float lw = __shfl_up_sync(0xFFFFFFFFu, a.w, 1);   // col tc-1
                float rx = __shfl_down_sync(0xFFFFFFFFu, a.x, 1); // col tc+4
                float ry = __shfl_down_sync(0xFFFFFFFFu, a.y, 1); // col tc+5
                if (ct == 0)  { lz = -INFINITY; lw = -INFINITY; } // image left border
                if (ct == 15) { rx = -INFINITY; ry = -INFINITY; } // image right border

                float cyz = fmaxf(a.y, a.z);
                float cxw = fmaxf(a.x, a.w);
                float m4  = fmaxf(cyz, cxw);                 // max(x,y,z,w)
                float4 h;
                h.x = fmaxf(fmaxf(lz, lw), fmaxf(a.x, cyz));    // cols tc-2..tc+2
                h.y = fmaxf(lw, m4);                            // cols tc-1..tc+3
                h.z = fmaxf(m4, rx);                            // cols tc  ..tc+4
                h.w = fmaxf(cyz, fmaxf(a.w, fmaxf(rx, ry)));    // cols tc+1..tc+5
                v[p][rr] = h;                                   // H result replaces input
                *(float4*)&s[p][tr + rr + ROFF][tc] = h;        // row exchange for V halo
            }
        }
        __syncthreads();

        // ---- vertical window-5 max in registers; store to output group g ----
        #pragma unroll
        for (int p = 0; p < 2; p++) {
            // halo rows: tr-2, tr-1, tr+4, tr+5 (padded indices tr+0, tr+1, tr+6, tr+7)
            float4 um2 = *(const float4*)&s[p][tr + 0][tc];
            float4 um1 = *(const float4*)&s[p][tr + 1][tc];
            float4 up4 = *(const float4*)&s[p][tr + 6][tc];
            float4 up5 = *(const float4*)&s[p][tr + 7][tc];

            float4 m12 = fmax4(v[p][1], v[p][2]);
            float4 m03 = fmax4(v[p][0], v[p][3]);
            float4 m4  = fmax4(m12, m03);
            float4 y0 = fmax4(fmax4(um2, um1), fmax4(v[p][0], m12));
            float4 y1 = fmax4(um1, m4);
            float4 y2 = fmax4(m4, up4);
            float4 y3 = fmax4(m12, fmax4(v[p][3], fmax4(up4, up5)));

            float4* og = ogp + (size_t)g * (NCH * PLANE / 4) + p * (PLANE / 4);
            __stcs(og +  0, y0);
            __stcs(og + 16, y1);
            __stcs(og + 32, y2);
            __stcs(og + 48, y3);

            v[p][0] = y0; v[p][1] = y1; v[p][2] = y2; v[p][3] = y3;
        }
        if (g < 3) __syncthreads();   // WAR: next pool rewrites s
    }
}

extern "C" void kernel_launch(void* const* d_in, const int* in_sizes, int n_in,
                              void* d_out, int out_size) {
    const float* x = (const float*)d_in[0];
    float* out = (float*)d_out;
    // 2048 blocks × 2 planes = 4096 planes
    spp_kernel<<<2048, 256>>>(x, out);
}